// round 16
// baseline (speedup 1.0000x reference)
#include <cuda_runtime.h>
#include <cuda_fp16.h>
#include <cstdint>

#define NN 512
#define CC 64
#define RR 32
#define BT 64
#define NT 128

typedef unsigned long long ull;

// mma n-column for physical channel f (each thread owns 8 contiguous f)
#define PERMN(f) (((f) & 32) + ((((f) & 7) >> 1) << 3) + ((((f) >> 3) & 3) << 1) + ((f) & 1))

// smem layout (uint32 units): fp16 pair-packed
#define OFF_W1   0        // [64 n][16]          | sPart overlay
#define OFF_W2   1024     // [64 n][36]          |
#define OFF_H    3328     // 2 x [64 b][36] (double-buffered)
#define SMEM_U32 7936
#define SMEM_BYTES (SMEM_U32 * 4)   // 31744 B

// prep buffers
__device__ uint32_t g_rbfh[(size_t)NN * NN * 16];    // fp16-pair GEMM1 A fragments
__device__ float    g_x0f[4 * NN * 16];              // [slot=ph*2+nh][row][16] fp32 pairs
__device__ float    g_x1f[12 * NN * 16];             // [slot=c*4+ph*2+nh][row][16] fp32 pairs
__device__ float    g_upx[(size_t)NN * NN * 12];     // [a*512+row][12]: u0u0u1u1 u2u2 -u0-u0 -u1-u1 -u2-u2

extern __shared__ float smem[];

__device__ __forceinline__ uint32_t pack_h2(float lo, float hi) {
    uint32_t r;
    asm("cvt.rn.f16x2.f32 %0, %1, %2;" : "=r"(r) : "f"(hi), "f"(lo));
    return r;
}
__device__ __forceinline__ uint32_t hmax2_zero(uint32_t v) {
    uint32_t r;
    asm("max.f16x2 %0, %1, %2;" : "=r"(r) : "r"(v), "r"(0u));
    return r;
}

__device__ __forceinline__ ull pk2(float lo, float hi) {
    ull d;
    asm("mov.b64 %0, {%1, %2};" : "=l"(d) : "f"(lo), "f"(hi));
    return d;
}
__device__ __forceinline__ void upk2(float& lo, float& hi, ull v) {
    asm("mov.b64 {%0, %1}, %2;" : "=f"(lo), "=f"(hi) : "l"(v));
}
__device__ __forceinline__ ull fma2(ull a, ull b, ull c) {
    ull d;
    asm("fma.rn.f32x2 %0, %1, %2, %3;" : "=l"(d) : "l"(a), "l"(b), "l"(c));
    return d;
}
__device__ __forceinline__ ull mul2(ull a, ull b) {
    ull d;
    asm("mul.rn.f32x2 %0, %1, %2;" : "=l"(d) : "l"(a), "l"(b));
    return d;
}

__device__ __forceinline__ void mma_f16(float c[4], uint32_t a0, uint32_t a1,
                                        uint32_t a2, uint32_t a3,
                                        uint32_t b0, uint32_t b1) {
    asm volatile(
        "mma.sync.aligned.m16n8k16.row.col.f32.f16.f16.f32 "
        "{%0,%1,%2,%3}, {%4,%5,%6,%7}, {%8,%9}, {%0,%1,%2,%3};"
        : "+f"(c[0]), "+f"(c[1]), "+f"(c[2]), "+f"(c[3])
        : "r"(a0), "r"(a1), "r"(a2), "r"(a3), "r"(b0), "r"(b1));
}

// ---- prep 1: rbf fp32 -> fp16-pair fragment layout ----
__global__ void prep_rbfh_kernel(const float* __restrict__ grbf) {
    int idx  = blockIdx.x * 256 + threadIdx.x;    // NN*NN*4
    int cpos = idx & 3;
    int rid  = idx >> 2;
    const float* src = grbf + (size_t)rid * RR;
    float2 p0 = *(const float2*)(src + 2 * cpos);
    float2 p1 = *(const float2*)(src + 2 * cpos + 8);
    float2 p2 = *(const float2*)(src + 2 * cpos + 16);
    float2 p3 = *(const float2*)(src + 2 * cpos + 24);
    uint4 v;
    v.x = pack_h2(p0.x, p0.y);
    v.y = pack_h2(p1.x, p1.y);
    v.z = pack_h2(p2.x, p2.y);
    v.w = pack_h2(p3.x, p3.y);
    *(uint4*)(g_rbfh + (size_t)rid * 16 + cpos * 4) = v;
}

// ---- prep 2: u broadcast/neg pairs + x0/x1 fp32 planar-pair repack ----
__global__ void prep_misc_kernel(const float* __restrict__ gx0,
                                 const float* __restrict__ gx1,
                                 const float* __restrict__ gu) {
    int idx = blockIdx.x * 256 + threadIdx.x;
    if (idx < NN * NN * 3) {
        int part = idx % 3;
        int rid  = idx / 3;
        const float* s = gu + (size_t)rid * 3;
        float u0 = s[0], u1 = s[1], u2 = s[2];
        float4 v;
        if (part == 0)      v = make_float4(u0, u0, u1, u1);
        else if (part == 1) v = make_float4(u2, u2, -u0, -u0);
        else                v = make_float4(-u1, -u1, -u2, -u2);
        *(float4*)&g_upx[(size_t)rid * 12 + part * 4] = v;
    } else {
        int j = idx - NN * NN * 3;
        if (j < 4 * NN * 4) {                     // x0f
            int cpos = j & 3, row = (j >> 2) & 511, slot = j >> 11;   // slot=ph*2+nh
            int ph = slot >> 1, nh = slot & 1;
            const float* s = gx0 + row * 64 + nh * 32 + cpos * 8 + ph * 4;
            *(float4*)&g_x0f[((size_t)slot * NN + row) * 16 + cpos * 4] =
                make_float4(s[0], s[1], s[2], s[3]);
        } else {                                  // x1f
            int j2 = j - 4 * NN * 4;
            int cpos = j2 & 3, row = (j2 >> 2) & 511, slot = j2 >> 11; // slot=c*4+ph*2+nh
            int nh = slot & 1, ph = (slot >> 1) & 1, c = slot >> 2;
            int fb = nh * 32 + cpos * 8 + ph * 4;
            const float* s = gx1 + row * 192;
            *(float4*)&g_x1f[((size_t)slot * NN + row) * 16 + cpos * 4] =
                make_float4(s[(fb + 0) * 3 + c], s[(fb + 1) * 3 + c],
                            s[(fb + 2) * 3 + c], s[(fb + 3) * 3 + c]);
        }
    }
}

__global__ __launch_bounds__(NT, 4)
void conv_tfn_h20_kernel(const float* __restrict__ gw1,
                         const float* __restrict__ gb1,
                         const float* __restrict__ gw2,
                         const float* __restrict__ gb2,
                         float* __restrict__ out)
{
    const int a    = blockIdx.x;
    const int m    = blockIdx.y;
    const int tid  = threadIdx.x;
    const int w    = tid >> 5;
    const int lane = tid & 31;
    const int mt    = w >> 1;
    const int nhalf = w & 1;
    const int r0    = lane >> 2;
    const int cpos  = lane & 3;

    uint32_t* sW1h = (uint32_t*)smem + OFF_W1;
    uint32_t* sW2h = (uint32_t*)smem + OFF_W2;
    uint32_t* sHb  = (uint32_t*)smem + OFF_H;

    // ---- stage weights as fp16 pairs (permuted-n cols, frag k-slots) ----
    {
        const float* p = gw1 + (size_t)m * RR * CC;
        for (int i = tid; i < CC * 16; i += NT) {
            int f = i & 63, q = i >> 6;
            int slot = (q & 3) * 4 + (q >> 3) * 2 + ((q >> 2) & 1);
            sW1h[PERMN(f) * 16 + slot] = pack_h2(p[(2 * q) * CC + f], p[(2 * q + 1) * CC + f]);
        }
        const float* qq = gw2 + (size_t)m * CC * CC;
        for (int i = tid; i < CC * 32; i += NT) {
            int f = i & 63, q = i >> 6;
            int slot = (q & 3) * 8 + (q >> 4) * 4 + ((q >> 3) & 1) * 2 + ((q >> 2) & 1);
            sW2h[PERMN(f) * 36 + slot] = pack_h2(qq[(2 * q) * CC + f], qq[(2 * q + 1) * CC + f]);
        }
    }

    const int fbase = nhalf * 32 + cpos * 8;

    float b1r[8], b2r[8];
    {
        float4 t0 = *(const float4*)(gb1 + m * CC + fbase);
        float4 t1 = *(const float4*)(gb1 + m * CC + fbase + 4);
        b1r[0]=t0.x; b1r[1]=t0.y; b1r[2]=t0.z; b1r[3]=t0.w;
        b1r[4]=t1.x; b1r[5]=t1.y; b1r[6]=t1.z; b1r[7]=t1.w;
        float4 s0 = *(const float4*)(gb2 + m * CC + fbase);
        float4 s1 = *(const float4*)(gb2 + m * CC + fbase + 4);
        b2r[0]=s0.x; b2r[1]=s0.y; b2r[2]=s0.z; b2r[3]=s0.w;
        b2r[4]=s1.x; b2r[5]=s1.y; b2r[6]=s1.z; b2r[7]=s1.w;
    }

    __syncthreads();   // weights visible

    // ---- hoist W1 B-fragments (16 regs); W2 stays in smem ----
    uint32_t w1b[4][4];
    #pragma unroll
    for (int nt = 0; nt < 4; nt++) {
        const int n = nhalf * 32 + nt * 8 + r0;
        *(uint4*)w1b[nt] = *(const uint4*)&sW1h[n * 16 + cpos * 4];
    }

    ull acc2[4][3];   // [q-pair][component], f32x2 accumulators
    #pragma unroll
    for (int i = 0; i < 4; i++) { acc2[i][0] = 0; acc2[i][1] = 0; acc2[i][2] = 0; }

    const int rbase = mt * 32 + r0;
    const int nrow  = nhalf * 32 + r0;
    const uint32_t* rbA = g_rbfh + (size_t)a * NN * 16;
    const float*    upA = g_upx + (size_t)a * NN * 12;

    int hb = 0;
    for (int bt = 0; bt < NN; bt += BT, hb ^= 1) {
        uint32_t* sHh = sHb + hb * 2304;

        // ---- GEMM1 + epilogue, per 16-row subtile (bias folded into C-init) ----
        #pragma unroll
        for (int s = 0; s < 2; s++) {
            const int R = rbase + s * 16;
            uint4 va = *(const uint4*)&rbA[(size_t)(bt + R) * 16 + cpos * 4];
            uint4 vb = *(const uint4*)&rbA[(size_t)(bt + R + 8) * 16 + cpos * 4];
            float hc[4][4];
            #pragma unroll
            for (int nt = 0; nt < 4; nt++) {
                hc[nt][0] = b1r[2*nt]; hc[nt][1] = b1r[2*nt+1];
                hc[nt][2] = b1r[2*nt]; hc[nt][3] = b1r[2*nt+1];
            }
            #pragma unroll
            for (int nt = 0; nt < 4; nt++) {
                mma_f16(hc[nt], va.x, vb.x, va.y, vb.y, w1b[nt][0], w1b[nt][1]);
                mma_f16(hc[nt], va.z, vb.z, va.w, vb.w, w1b[nt][2], w1b[nt][3]);
            }
            // relu on packed fp16 pairs
            #pragma unroll
            for (int nt = 0; nt < 4; nt++) {
                const int sl = nt * 8 + nhalf * 4 + cpos;
                sHh[R * 36 + sl]       = hmax2_zero(pack_h2(hc[nt][0], hc[nt][1]));
                sHh[(R + 8) * 36 + sl] = hmax2_zero(pack_h2(hc[nt][2], hc[nt][3]));
            }
        }
        // single pair barrier per tile (double-buffered H)
        asm volatile("bar.sync %0, %1;" :: "r"(1 + mt), "r"(64) : "memory");

        // ---- GEMM2 + contraction, per 16-row subtile (b2 folded into C-init) ----
        #pragma unroll
        for (int s = 0; s < 2; s++) {
            const int R = rbase + s * 16;
            uint4 x00 = *(const uint4*)&sHh[R * 36 + cpos * 8];
            uint4 x01 = *(const uint4*)&sHh[R * 36 + cpos * 8 + 4];
            uint4 x10 = *(const uint4*)&sHh[(R + 8) * 36 + cpos * 8];
            uint4 x11 = *(const uint4*)&sHh[(R + 8) * 36 + cpos * 8 + 4];
            float rc[4][4];
            #pragma unroll
            for (int nt = 0; nt < 4; nt++) {
                rc[nt][0] = b2r[2*nt]; rc[nt][1] = b2r[2*nt+1];
                rc[nt][2] = b2r[2*nt]; rc[nt][3] = b2r[2*nt+1];
            }
            #pragma unroll
            for (int nt = 0; nt < 4; nt++) {
                const int n = nrow + nt * 8;
                uint4 B0 = *(const uint4*)&sW2h[n * 36 + cpos * 8];
                uint4 B1 = *(const uint4*)&sW2h[n * 36 + cpos * 8 + 4];
                mma_f16(rc[nt], x00.x, x10.x, x00.y, x10.y, B0.x, B0.y);
                mma_f16(rc[nt], x00.z, x10.z, x00.w, x10.w, B0.z, B0.w);
                mma_f16(rc[nt], x01.x, x11.x, x01.y, x11.y, B1.x, B1.y);
                mma_f16(rc[nt], x01.z, x11.z, x01.w, x11.w, B1.z, B1.w);
            }

            #pragma unroll
            for (int rs = 0; rs < 2; rs++) {
                const int grow = bt + R + rs * 8;
                if (grow == a) continue;   // diagonal mask

                ull rad2[4];
                #pragma unroll
                for (int i = 0; i < 4; i++)
                    rad2[i] = pk2(rc[i][rs * 2], rc[i][rs * 2 + 1]);   // bias already in

                if (m <= 1) {
                    ulonglong2 Xa = *(const ulonglong2*)&g_x0f[((size_t)(0 + nhalf) * NN + grow) * 16 + cpos * 4];
                    ulonglong2 Xb = *(const ulonglong2*)&g_x0f[((size_t)(2 + nhalf) * NN + grow) * 16 + cpos * 4];
                    ull X[4] = {Xa.x, Xa.y, Xb.x, Xb.y};
                    if (m == 0) {
                        #pragma unroll
                        for (int i = 0; i < 4; i++)
                            acc2[i][0] = fma2(rad2[i], X[i], acc2[i][0]);
                    } else {
                        ulonglong2 Ua = *(const ulonglong2*)&upA[(size_t)grow * 12];
                        ull U2bc = *(const ull*)&upA[(size_t)grow * 12 + 4];
                        #pragma unroll
                        for (int i = 0; i < 4; i++) {
                            ull t = mul2(rad2[i], X[i]);
                            acc2[i][0] = fma2(Ua.x, t, acc2[i][0]);
                            acc2[i][1] = fma2(Ua.y, t, acc2[i][1]);
                            acc2[i][2] = fma2(U2bc, t, acc2[i][2]);
                        }
                    }
                } else {
                    ulonglong2 XXa = *(const ulonglong2*)&g_x1f[((size_t)(0 + nhalf) * NN + grow) * 16 + cpos * 4];
                    ulonglong2 XXb = *(const ulonglong2*)&g_x1f[((size_t)(2 + nhalf) * NN + grow) * 16 + cpos * 4];
                    ulonglong2 XYa = *(const ulonglong2*)&g_x1f[((size_t)(4 + nhalf) * NN + grow) * 16 + cpos * 4];
                    ulonglong2 XYb = *(const ulonglong2*)&g_x1f[((size_t)(6 + nhalf) * NN + grow) * 16 + cpos * 4];
                    ulonglong2 XZa = *(const ulonglong2*)&g_x1f[((size_t)(8 + nhalf) * NN + grow) * 16 + cpos * 4];
                    ulonglong2 XZb = *(const ulonglong2*)&g_x1f[((size_t)(10 + nhalf) * NN + grow) * 16 + cpos * 4];
                    ull XX[4] = {XXa.x, XXa.y, XXb.x, XXb.y};
                    ull XY[4] = {XYa.x, XYa.y, XYb.x, XYb.y};
                    ull XZ[4] = {XZa.x, XZa.y, XZb.x, XZb.y};
                    if (m == 2) {
                        #pragma unroll
                        for (int i = 0; i < 4; i++) {
                            acc2[i][0] = fma2(rad2[i], XX[i], acc2[i][0]);
                            acc2[i][1] = fma2(rad2[i], XY[i], acc2[i][1]);
                            acc2[i][2] = fma2(rad2[i], XZ[i], acc2[i][2]);
                        }
                    } else if (m == 3) {
                        ulonglong2 Ua = *(const ulonglong2*)&upA[(size_t)grow * 12];
                        ull U2bc = *(const ull*)&upA[(size_t)grow * 12 + 4];
                        #pragma unroll
                        for (int i = 0; i < 4; i++) {
                            ull d = mul2(Ua.x, XX[i]);
                            d = fma2(Ua.y, XY[i], d);
                            d = fma2(U2bc, XZ[i], d);
                            acc2[i][0] = fma2(rad2[i], d, acc2[i][0]);
                        }
                    } else {   // m == 4 : cross product u x x1
                        ulonglong2 Ua = *(const ulonglong2*)&upA[(size_t)grow * 12];      // u0,u1
                        ulonglong2 Ub = *(const ulonglong2*)&upA[(size_t)grow * 12 + 4];  // u2,-u0
                        ulonglong2 Uc = *(const ulonglong2*)&upA[(size_t)grow * 12 + 8];  // -u1,-u2
                        #pragma unroll
                        for (int i = 0; i < 4; i++) {
                            ull cx = fma2(Uc.y, XY[i], mul2(Ua.y, XZ[i]));   // u1*xz - u2*xy
                            ull cy = fma2(Ub.y, XZ[i], mul2(Ub.x, XX[i]));   // u2*xx - u0*xz
                            ull cz = fma2(Uc.x, XX[i], mul2(Ua.x, XY[i]));   // u0*xy - u1*xx
                            acc2[i][0] = fma2(rad2[i], cx, acc2[i][0]);
                            acc2[i][1] = fma2(rad2[i], cy, acc2[i][1]);
                            acc2[i][2] = fma2(rad2[i], cz, acc2[i][2]);
                        }
                    }
                }
            }
        }
    }

    // ---- cross-thread reduction (16 contributors per output channel) ----
    __syncthreads();
    float* sPart = smem;   // W1/W2 regions dead; 3072 <= 3328 floats
    {
        const int base = tid * 24;
        #pragma unroll
        for (int i = 0; i < 4; i++)
            #pragma unroll
            for (int c = 0; c < 3; c++) {
                float lo, hi;
                upk2(lo, hi, acc2[i][c]);
                sPart[base + (2 * i) * 3 + c]     = lo;
                sPart[base + (2 * i + 1) * 3 + c] = hi;
            }
    }
    __syncthreads();

    const float nm = rsqrtf((float)(NN - 1));
    float* out1 = out + NN * 2 * CC;

    for (int idx = tid; idx < CC * 3; idx += NT) {
        const int f    = idx / 3;
        const int comp = idx - f * 3;
        const int nh = f >> 5;
        const int cp = (f >> 3) & 3;
        const int q  = f & 7;
        float s = 0.0f;
        #pragma unroll
        for (int mm = 0; mm < 2; mm++) {
            #pragma unroll
            for (int rg = 0; rg < 8; rg++) {
                int tc = (mm * 2 + nh) * 32 + rg * 4 + cp;
                s += sPart[tc * 24 + q * 3 + comp];
            }
        }
        s *= nm;

        if (m == 0)      { if (comp == 0) out[a * 128 + f] = s; }
        else if (m == 1) { out1[a * 576 + f * 3 + comp] = s; }
        else if (m == 2) { out1[a * 576 + (64 + f) * 3 + comp] = s; }
        else if (m == 3) { if (comp == 0) out[a * 128 + 64 + f] = s; }
        else             { out1[a * 576 + (128 + f) * 3 + comp] = s; }
    }
}

extern "C" void kernel_launch(void* const* d_in, const int* in_sizes, int n_in,
                              void* d_out, int out_size) {
    const float* x0  = (const float*)d_in[0];
    const float* x1  = (const float*)d_in[1];
    const float* rbf = (const float*)d_in[2];
    const float* u   = (const float*)d_in[3];
    // d_in[4] = r_ij : unused (switching_fn == None)
    const float* w1  = (const float*)d_in[5];
    const float* b1  = (const float*)d_in[6];
    const float* w2  = (const float*)d_in[7];
    const float* b2  = (const float*)d_in[8];
    float* out = (float*)d_out;

    prep_rbfh_kernel<<<(NN * NN * 4) / 256, 256>>>(rbf);
    prep_misc_kernel<<<(NN * NN * 3 + 4 * NN * 4 + 12 * NN * 4) / 256, 256>>>(x0, x1, u);

    cudaFuncSetAttribute(conv_tfn_h20_kernel,
                         cudaFuncAttributeMaxDynamicSharedMemorySize, SMEM_BYTES);
    dim3 grid(NN, 5);
    conv_tfn_h20_kernel<<<grid, NT, SMEM_BYTES>>>(w1, b1, w2, b2, out);
}